// round 11
// baseline (speedup 1.0000x reference)
#include <cuda_runtime.h>
#include <stdint.h>

// KVCache_9526237462719:
//   input_pos: int32[S], k_val/v_val: f32[B,H,S,D], k_cache/v_cache: f32[B,H,BLOCK,D]
//   out = [k_cache.at[:,:,pos].set(k_val)[:,:,:S,:], same for v] concat, f32.
#define KB      4
#define KH      32
#define KS      1024
#define KD      128
#define KBLOCK  4096

#define D4      (KD / 4)                 // 32 float4 per row
#define HALF4   (4u * KH * KS * D4)      // 4,194,304 = 2^22
#define TOTAL4  (2u * HALF4)             // 8,388,608 = 2^23

#define NTHREADS 512
#define NBLOCKS  8192                    // 8192*512 = 2^22 threads
#define STRIDE   (1u << 22)              // 2 slots * STRIDE = TOTAL4

// Retained-subset threshold: bh < 96 loads use default policy (L2-resident
// across replays: 96 slices * 2 tensors * 512 KB = 96 MB < 126 MB L2);
// bh >= 96 loads stream with .cs. Stores stay .cs so the write stream
// preferentially evicts itself / streamed lines, not the resident set.
#define BH_RETAIN 96u

__global__ __launch_bounds__(NTHREADS)
void kv_fused_kernel(const int*    __restrict__ input_pos,
                     const float4* __restrict__ k_val,
                     const float4* __restrict__ v_val,
                     const float4* __restrict__ k_cache,
                     const float4* __restrict__ v_cache,
                     float4*       __restrict__ out) {
    // i0 in [0, 2^22); slot 0 -> K half, slot 1 -> V half (compile-time).
    // d4, p, bh invariant across slots (2^22 is a multiple of S*D4 = 2^15).
    unsigned i0 = blockIdx.x * NTHREADS + threadIdx.x;
    unsigned d4 = i0 & (D4 - 1);
    unsigned r0 = i0 >> 5;
    unsigned p  = r0 & (KS - 1);
    unsigned bh = r0 >> 10;               // < 128

    // inv[p]: which source s wrote position p (−1 if none).
    int s;
    if (__ldg(input_pos + p) == (int)p) {
        s = (int)p;                       // fast path (always taken here)
    } else {
        s = -1;                           // general fallback: last writer wins
        for (int t = 0; t < KS; t++) {
            if (__ldg(input_pos + t) == (int)p) s = t;
        }
    }

    const float4* ksrc;
    const float4* vsrc;
    if (s >= 0) {
        size_t off = (size_t)(bh * (KS * D4) + (unsigned)s * D4 + d4);
        ksrc = k_val + off;
        vsrc = v_val + off;
    } else {
        size_t off = (size_t)(bh * (KBLOCK * D4) + p * D4 + d4);
        ksrc = k_cache + off;
        vsrc = v_cache + off;
    }

    float4 rk, rv;
    if (bh < BH_RETAIN) {
        rk = *ksrc;                       // default: retain in L2 across replays
        rv = *vsrc;
    } else {
        rk = __ldcs(ksrc);                // stream: evict-first
        rv = __ldcs(vsrc);
    }

    // Evict-first stores (write stream does not displace the resident set).
    __stcs(out + i0, rk);
    __stcs(out + i0 + STRIDE, rv);
}

extern "C" void kernel_launch(void* const* d_in, const int* in_sizes, int n_in,
                              void* d_out, int out_size) {
    const int*    input_pos = (const int*)d_in[0];
    const float4* k_val     = (const float4*)d_in[1];
    const float4* v_val     = (const float4*)d_in[2];
    const float4* k_cache   = (const float4*)d_in[3];
    const float4* v_cache   = (const float4*)d_in[4];
    float4*       out       = (float4*)d_out;

    kv_fused_kernel<<<NBLOCKS, NTHREADS>>>(input_pos, k_val, v_val,
                                           k_cache, v_cache, out);
}

// round 12
// speedup vs baseline: 1.0375x; 1.0375x over previous
#include <cuda_runtime.h>
#include <stdint.h>

// KVCache_9526237462719:
//   input_pos: int32[S], k_val/v_val: f32[B,H,S,D], k_cache/v_cache: f32[B,H,BLOCK,D]
//   out = [k_cache.at[:,:,pos].set(k_val)[:,:,:S,:], same for v] concat, f32.
#define KB      4
#define KH      32
#define KS      1024
#define KD      128
#define KBLOCK  4096

#define D4      (KD / 4)                 // 32 float4 per row
#define HALF4   (4u * KH * KS * D4)      // 4,194,304 = 2^22
#define TOTAL4  (2u * HALF4)             // 8,388,608 = 2^23

#define NTHREADS 512
#define NBLOCKS  8192                    // 8192*512 = 2^22 threads
#define STRIDE   (1u << 22)              // 2 slots * STRIDE = TOTAL4

// Policy probe: DEFAULT loads and DEFAULT stores. The output buffer is
// rewritten every graph replay, so under default policy its lines can stay
// dirty-resident in L2 across replays: full-line write HITS absorb at L2
// bandwidth and DRAM write-back is deferred/overlapped. (Grid of prior
// results at this structure: ldcs/stcs 44.6, default/stcs 43.5,
// default/stwt 44.5, partitioned/stcs 45.1.)
// No smem, no barriers; inv[p] via warp-uniform speculative probe.
__global__ __launch_bounds__(NTHREADS)
void kv_fused_kernel(const int*    __restrict__ input_pos,
                     const float4* __restrict__ k_val,
                     const float4* __restrict__ v_val,
                     const float4* __restrict__ k_cache,
                     const float4* __restrict__ v_cache,
                     float4*       __restrict__ out) {
    // i0 in [0, 2^22); slot 0 -> K half, slot 1 -> V half (compile-time).
    // d4, p, bh invariant across slots (2^22 is a multiple of S*D4 = 2^15).
    unsigned i0 = blockIdx.x * NTHREADS + threadIdx.x;
    unsigned d4 = i0 & (D4 - 1);
    unsigned r0 = i0 >> 5;
    unsigned p  = r0 & (KS - 1);
    unsigned bh = r0 >> 10;               // < 128

    // inv[p]: which source s wrote position p (−1 if none).
    int s;
    if (__ldg(input_pos + p) == (int)p) {
        s = (int)p;                       // fast path (always taken here)
    } else {
        s = -1;                           // general fallback: last writer wins
        for (int t = 0; t < KS; t++) {
            if (__ldg(input_pos + t) == (int)p) s = t;
        }
    }

    const float4* ksrc;
    const float4* vsrc;
    if (s >= 0) {
        size_t off = (size_t)(bh * (KS * D4) + (unsigned)s * D4 + d4);
        ksrc = k_val + off;
        vsrc = v_val + off;
    } else {
        size_t off = (size_t)(bh * (KBLOCK * D4) + p * D4 + d4);
        ksrc = k_cache + off;
        vsrc = v_cache + off;
    }

    // Default-policy loads and stores (maximize cross-replay L2 reuse).
    float4 rk = *ksrc;
    float4 rv = *vsrc;
    out[i0]          = rk;
    out[i0 + STRIDE] = rv;
}

extern "C" void kernel_launch(void* const* d_in, const int* in_sizes, int n_in,
                              void* d_out, int out_size) {
    const int*    input_pos = (const int*)d_in[0];
    const float4* k_val     = (const float4*)d_in[1];
    const float4* v_val     = (const float4*)d_in[2];
    const float4* k_cache   = (const float4*)d_in[3];
    const float4* v_cache   = (const float4*)d_in[4];
    float4*       out       = (float4*)d_out;

    kv_fused_kernel<<<NBLOCKS, NTHREADS>>>(input_pos, k_val, v_val,
                                           k_cache, v_cache, out);
}